// round 13
// baseline (speedup 1.0000x reference)
#include <cuda_runtime.h>
#include <cuda_bf16.h>
#include <cstdint>

#define CN0 2048
#define CN1 8192
#define CN2 4096

// ---------------------------------------------------------------------------
// Scratch (device globals — no allocation allowed)
// ---------------------------------------------------------------------------
__device__ float g_X0cat[CN0 * 256];   // [x0 | x0p]
__device__ float g_T10[CN0 * 256];
__device__ float g_T20[CN0 * 256];
__device__ float g_X1cat[CN1 * 256];   // [x1 | x1p]
__device__ float g_T1l[CN1 * 128];
__device__ float g_T2l[CN1 * 128];
__device__ float g_T1u[CN1 * 256];
__device__ float g_T2u[CN1 * 256];
__device__ float g_X2cat[CN2 * 256];   // [x2n | x2]
__device__ float g_T12[CN2 * 256];
__device__ float g_T22[CN2 * 256];
__device__ float g_W0[6 * 16384];      // repacked [c][i][o]
__device__ float g_W1[8 * 16384];
__device__ float g_W2[6 * 16384];
__device__ float g_x1s[CN1 * 128];     // d5_pinv * x1 (pre-scaled)
__device__ float g_x2s[CN2 * 128];     // d3 * x2 (pre-scaled)

// ---------------------------------------------------------------------------
// Helpers (sm_80-level features ONLY — harness compiles for plain sm_103)
// ---------------------------------------------------------------------------
__device__ __forceinline__ uint32_t smem_u32(const void* p) {
    uint32_t a;
    asm("{ .reg .u64 t; cvta.to.shared.u64 t, %1; cvt.u32.u64 %0, t; }"
        : "=r"(a) : "l"(p));
    return a;
}
__device__ __forceinline__ uint32_t swz(uint32_t off) {
    return off ^ ((off >> 3) & 0x70u);   // SW128 swizzle for 128B rows
}
__device__ __forceinline__ void ldm4(uint32_t addr, uint32_t r[4]) {
    asm volatile("ldmatrix.sync.aligned.m8n8.x4.shared.b16 {%0,%1,%2,%3}, [%4];"
                 : "=r"(r[0]), "=r"(r[1]), "=r"(r[2]), "=r"(r[3]) : "r"(addr));
}
__device__ __forceinline__ void mma16816(float d[4], const uint32_t a[4],
                                         uint32_t b0, uint32_t b1) {
    asm volatile("mma.sync.aligned.m16n8k16.row.col.f32.bf16.bf16.f32 "
                 "{%0,%1,%2,%3}, {%4,%5,%6,%7}, {%8,%9}, {%0,%1,%2,%3};"
                 : "+f"(d[0]), "+f"(d[1]), "+f"(d[2]), "+f"(d[3])
                 : "r"(a[0]), "r"(a[1]), "r"(a[2]), "r"(a[3]), "r"(b0), "r"(b1));
}

// ---------------------------------------------------------------------------
// bf16 hi/lo split + swizzled STS
// ---------------------------------------------------------------------------
__device__ __forceinline__ void split8(const float4& v0, const float4& v1,
                                       uint4& hi, uint4& lo) {
    float a[8] = {v0.x, v0.y, v0.z, v0.w, v1.x, v1.y, v1.z, v1.w};
    uint32_t h[4], l[4];
#pragma unroll
    for (int p = 0; p < 4; p++) {
        __nv_bfloat162 hb = __floats2bfloat162_rn(a[2 * p], a[2 * p + 1]);
        float hx = __bfloat162float(hb.x), hy = __bfloat162float(hb.y);
        __nv_bfloat162 lb = __floats2bfloat162_rn(a[2 * p] - hx, a[2 * p + 1] - hy);
        h[p] = *(uint32_t*)&hb;
        l[p] = *(uint32_t*)&lb;
    }
    hi = make_uint4(h[0], h[1], h[2], h[3]);
    lo = make_uint4(l[0], l[1], l[2], l[3]);
}
__device__ __forceinline__ void sts128(char* base, uint32_t off, const uint4& v) {
    *(uint4*)(base + swz(off)) = v;
}

// ---------------------------------------------------------------------------
// Half-chunk staged loaders. CTA tile: A [256m x 64k], B [128n x 64k].
// A half = 256m x 32k (8 float4/thread); B half = 128n x 32k (4 float4/thread).
// 256 threads. h = half index (0/1); within-panel byte row = 128B (K=64 row).
// ---------------------------------------------------------------------------
__device__ __forceinline__ void ldgA_n(float4* st, const float* __restrict__ A,
                                       int lda, int m0, int kb, int t) {
    const float* Ab = A + (size_t)m0 * lda + kb;
#pragma unroll
    for (int l = 0; l < 4; l++) {
        int idx = t + l * 256;
        int m = idx >> 2, kq = idx & 3;
        const float* p = Ab + (size_t)m * lda + kq * 8;
        st[2 * l]     = *(const float4*)p;
        st[2 * l + 1] = *(const float4*)(p + 4);
    }
}
__device__ __forceinline__ void stsA_n(char* hi, char* lo, const float4* st,
                                       int h, int t) {
#pragma unroll
    for (int l = 0; l < 4; l++) {
        int idx = t + l * 256;
        int m = idx >> 2, kq = idx & 3;
        uint4 hh, lw;
        split8(st[2 * l], st[2 * l + 1], hh, lw);
        uint32_t off = (uint32_t)(m * 128 + h * 64 + kq * 16);
        sts128(hi, off, hh);
        sts128(lo, off, lw);
    }
}
// Transposed A: m = t (0..255), kg = l (0..3), 8 strided k each
__device__ __forceinline__ void ldgA_t(float4* st, const float* __restrict__ A,
                                       int lda, int m0, int kb, int t) {
    const float* Ab = A + (size_t)kb * lda + m0 + t;
#pragma unroll
    for (int l = 0; l < 4; l++) {
        const float* p = Ab + (size_t)l * 8 * lda;
        float4 v0, v1;
        v0.x = p[0];
        v0.y = p[(size_t)lda];
        v0.z = p[(size_t)2 * lda];
        v0.w = p[(size_t)3 * lda];
        v1.x = p[(size_t)4 * lda];
        v1.y = p[(size_t)5 * lda];
        v1.z = p[(size_t)6 * lda];
        v1.w = p[(size_t)7 * lda];
        st[2 * l]     = v0;
        st[2 * l + 1] = v1;
    }
}
__device__ __forceinline__ void stsA_t(char* hi, char* lo, const float4* st,
                                       int h, int t) {
#pragma unroll
    for (int l = 0; l < 4; l++) {
        uint4 hh, lw;
        split8(st[2 * l], st[2 * l + 1], hh, lw);
        uint32_t off = (uint32_t)(t * 128 + h * 64 + l * 16);
        sts128(hi, off, hh);
        sts128(lo, off, lw);
    }
}
// B: k-major gather, n = t&127, kg = (t>>7)+2l (l=0..1)
__device__ __forceinline__ void ldgB(float4* st, const float* __restrict__ B,
                                     int ldb, int n0, int kb, int t) {
    int n = t & 127;
    const float* Bb = B + (size_t)kb * ldb + n0 + n;
#pragma unroll
    for (int l = 0; l < 2; l++) {
        int kg = (t >> 7) + 2 * l;
        const float* p = Bb + (size_t)kg * 8 * ldb;
        float4 v0, v1;
        v0.x = p[0];
        v0.y = p[(size_t)ldb];
        v0.z = p[(size_t)2 * ldb];
        v0.w = p[(size_t)3 * ldb];
        v1.x = p[(size_t)4 * ldb];
        v1.y = p[(size_t)5 * ldb];
        v1.z = p[(size_t)6 * ldb];
        v1.w = p[(size_t)7 * ldb];
        st[2 * l]     = v0;
        st[2 * l + 1] = v1;
    }
}
__device__ __forceinline__ void stsB(char* hi, char* lo, const float4* st,
                                     int h, int t) {
    int n = t & 127;
#pragma unroll
    for (int l = 0; l < 2; l++) {
        int kg = (t >> 7) + 2 * l;
        uint4 hh, lw;
        split8(st[2 * l], st[2 * l + 1], hh, lw);
        uint32_t off = (uint32_t)(n * 128 + h * 64 + kg * 16);
        sts128(hi, off, hh);
        sts128(lo, off, lw);
    }
}

// ---------------------------------------------------------------------------
// Batched GEMM descriptors
// ---------------------------------------------------------------------------
struct GemmDesc {
    const float* A;
    const float* B;
    const float* S;
    const float* crow;
    const float* Achan[8];
    float* C;
    int Alda[8];
    int lda, ldb, lds, ldc, crs;
    int K, ntiles, tile_base, transa, epi, nch;  // epi: 0=scale, 1=2AB-S, 2=relu
};
struct BatchArgs { GemmDesc d[4]; int nd; };

__device__ __forceinline__ void ldg_half(float4* stA, float4* stB, const GemmDesc& g,
                                         int m0, int n0, int k0, int h, int t) {
    int kb = k0 + h * 32;
    if (g.nch) {
        int c = k0 >> 7;
        int kin = (k0 & 127) + h * 32;
        ldgA_n(stA, g.Achan[c], g.Alda[c], m0, kin, t);
        ldgB(stB, g.B + (size_t)c * 16384, 128, 0, kin, t);
    } else if (g.transa) {
        ldgA_t(stA, g.A, g.lda, m0, kb, t);
        ldgB(stB, g.B, g.ldb, n0, kb, t);
    } else {
        ldgA_n(stA, g.A, g.lda, m0, kb, t);
        ldgB(stB, g.B, g.ldb, n0, kb, t);
    }
}
// Panel layout within stage: aHi 32KB | aLo 32KB | bHi 16KB | bLo 16KB
#define PAN_ALO 32768
#define PAN_BHI 65536
#define PAN_BLO 81920
#define STAGE_BYTES 98304
#define SMEM_BYTES (2 * STAGE_BYTES + 1024)

__device__ __forceinline__ void sts_half(char* stg, const float4* stA, const float4* stB,
                                         int amode, int h, int t) {
    if (amode) stsA_t(stg, stg + PAN_ALO, stA, h, t);
    else       stsA_n(stg, stg + PAN_ALO, stA, h, t);
    stsB(stg + PAN_BHI, stg + PAN_BLO, stB, h, t);
}

// Compute one K=32 half: warp tile 64m x 64n, 3-product bf16 compensation.
__device__ __forceinline__ void compute_half(uint32_t s, int wm, int wn, int lane,
                                             int half, float acc[4][8][4]) {
    uint32_t sAh = s, sAl = s + PAN_ALO, sBh = s + PAN_BHI, sBl = s + PAN_BLO;
#pragma unroll
    for (int kx = 0; kx < 2; kx++) {
        int kk = half * 2 + kx;
        uint32_t ah[4][4], al[4][4];
#pragma unroll
        for (int mt = 0; mt < 4; mt++) {
            uint32_t off = (uint32_t)((wm * 64 + mt * 16 + (lane & 15)) * 128
                                      + kk * 32 + ((lane >> 4) << 4));
            uint32_t so = swz(off);
            ldm4(sAh + so, ah[mt]);
            ldm4(sAl + so, al[mt]);
        }
        uint32_t bh[4][4], bl[4][4];
#pragma unroll
        for (int ng = 0; ng < 4; ng++) {
            int r = lane & 7, part = lane >> 3;
            int n = wn * 64 + ng * 16 + r + ((part >> 1) << 3);
            uint32_t off = (uint32_t)(n * 128 + kk * 32 + ((part & 1) << 4));
            uint32_t so = swz(off);
            ldm4(sBh + so, bh[ng]);
            ldm4(sBl + so, bl[ng]);
        }
#pragma unroll
        for (int mt = 0; mt < 4; mt++)
#pragma unroll
            for (int ng = 0; ng < 4; ng++)
#pragma unroll
                for (int hh = 0; hh < 2; hh++) {
                    int nt = ng * 2 + hh;
                    mma16816(acc[mt][nt], ah[mt], bh[ng][hh * 2], bh[ng][hh * 2 + 1]);
                    mma16816(acc[mt][nt], ah[mt], bl[ng][hh * 2], bl[ng][hh * 2 + 1]);
                    mma16816(acc[mt][nt], al[mt], bh[ng][hh * 2], bh[ng][hh * 2 + 1]);
                }
    }
}

__global__ __launch_bounds__(256, 1) void gemm_mma(BatchArgs args) {
    extern __shared__ char smem_raw[];
    uint32_t sb = smem_u32(smem_raw);
    uint32_t al1k = (sb + 1023u) & ~1023u;
    char* st0 = smem_raw + (al1k - sb);
    uint32_t sb0 = al1k;

    int t = threadIdx.x;
    int lane = t & 31;
    int warp = t >> 5;
    int wm = warp >> 1, wn = warp & 1;
    int bid = blockIdx.x;

    int di = 0;
#pragma unroll
    for (int i = 1; i < 4; i++)
        if (i < args.nd && bid >= args.d[i].tile_base) di = i;
    const GemmDesc& g = args.d[di];

    int tile = bid - g.tile_base;
    int bm = tile / g.ntiles;
    int bn = tile - bm * g.ntiles;
    int m0 = bm << 8, n0 = bn << 7;                 // 256m x 128n CTA tile
    int amode = (g.nch == 0 && g.transa) ? 1 : 0;

    float acc[4][8][4];
#pragma unroll
    for (int i = 0; i < 4; i++)
#pragma unroll
        for (int j = 0; j < 8; j++)
#pragma unroll
            for (int k = 0; k < 4; k++) acc[i][j][k] = 0.0f;

    int NC = g.K >> 6;

    float4 stA[8], stB[4];
    ldg_half(stA, stB, g, m0, n0, 0, 0, t);
    sts_half(st0, stA, stB, amode, 0, t);
    ldg_half(stA, stB, g, m0, n0, 0, 1, t);
    sts_half(st0, stA, stB, amode, 1, t);
    __syncthreads();

#pragma unroll 1
    for (int ci = 0; ci < NC; ci++) {
        int more = (ci + 1 < NC);
        char* nbuf = st0 + ((ci + 1) & 1) * STAGE_BYTES;
        uint32_t s = sb0 + (ci & 1) * STAGE_BYTES;
        if (more) ldg_half(stA, stB, g, m0, n0, (ci + 1) << 6, 0, t);
        compute_half(s, wm, wn, lane, 0, acc);
        if (more) {
            sts_half(nbuf, stA, stB, amode, 0, t);
            ldg_half(stA, stB, g, m0, n0, (ci + 1) << 6, 1, t);
        }
        compute_half(s, wm, wn, lane, 1, acc);
        if (more) sts_half(nbuf, stA, stB, amode, 1, t);
        __syncthreads();
    }

    // Epilogue: rows r0 = m0+wm*64+mt*16+(lane>>2), r1 = r0+8;
    //           cols c = n0+wn*64+nt*8+(lane&3)*2
    int ldc = g.ldc;
#pragma unroll
    for (int mt = 0; mt < 4; mt++) {
        int r0 = m0 + wm * 64 + mt * 16 + (lane >> 2);
        int r1 = r0 + 8;
        float s0 = 1.0f, s1 = 1.0f;
        if (g.epi == 0 && g.crow) {
            s0 = g.crow[(size_t)r0 * g.crs];
            s1 = g.crow[(size_t)r1 * g.crs];
        }
        float* C0 = g.C + (size_t)r0 * ldc;
        float* C1 = g.C + (size_t)r1 * ldc;
        const float* S0 = nullptr;
        const float* S1 = nullptr;
        if (g.epi == 1) {
            S0 = g.S + (size_t)r0 * g.lds;
            S1 = g.S + (size_t)r1 * g.lds;
        }
#pragma unroll
        for (int nt = 0; nt < 8; nt++) {
            int c = n0 + wn * 64 + nt * 8 + ((lane & 3) << 1);
            float d0 = acc[mt][nt][0], d1 = acc[mt][nt][1];
            float d2 = acc[mt][nt][2], d3 = acc[mt][nt][3];
            if (g.epi == 0) {
                *(float2*)(C0 + c) = make_float2(d0 * s0, d1 * s0);
                *(float2*)(C1 + c) = make_float2(d2 * s1, d3 * s1);
            } else if (g.epi == 1) {
                float2 sv0 = *(const float2*)(S0 + c);
                float2 sv1 = *(const float2*)(S1 + c);
                *(float2*)(C0 + c) = make_float2(2.f * d0 - sv0.x, 2.f * d1 - sv0.y);
                *(float2*)(C1 + c) = make_float2(2.f * d2 - sv1.x, 2.f * d3 - sv1.y);
            } else {
                *(float2*)(C0 + c) = make_float2(fmaxf(d0, 0.f), fmaxf(d1, 0.f));
                *(float2*)(C1 + c) = make_float2(fmaxf(d2, 0.f), fmaxf(d3, 0.f));
            }
        }
    }
}

// ---------------------------------------------------------------------------
// Prep kernels
// ---------------------------------------------------------------------------
__global__ void pack_kernel(float* __restrict__ dst, const float* __restrict__ w, int nk) {
    int idx = blockIdx.x * 256 + threadIdx.x;
    if (idx < 16384) {
        for (int c = 0; c < nk; c++) dst[c * 16384 + idx] = w[idx * nk + c];
    }
}
__global__ void copy_kernel(float* __restrict__ dst, const float* __restrict__ src, int rows) {
    int idx = blockIdx.x * 256 + threadIdx.x;
    int r = idx >> 5, q = (idx & 31) << 2;
    if (r < rows)
        *(float4*)(dst + (size_t)r * 256 + q) = *(const float4*)(src + (size_t)r * 128 + q);
}
__global__ void scale_copy_kernel(float* __restrict__ dst, const float* __restrict__ src,
                                  const float* __restrict__ diag, int ds, int rows) {
    int idx = blockIdx.x * 256 + threadIdx.x;
    int r = idx >> 5, q = (idx & 31) << 2;
    if (r < rows) {
        float s = diag[(size_t)r * ds];
        float4 v = *(const float4*)(src + (size_t)r * 128 + q);
        v.x *= s; v.y *= s; v.z *= s; v.w *= s;
        *(float4*)(dst + (size_t)r * 128 + q) = v;
    }
}

// ---------------------------------------------------------------------------
// Host launcher
// ---------------------------------------------------------------------------
static GemmDesc mk(const float* A, int lda, int ta,
                   const float* B, int ldb,
                   float* C, int ldc,
                   const float* cr, int crs,
                   const float* S, int lds,
                   int K, int ntiles, int base, int epi) {
    GemmDesc g{};
    g.A = A; g.lda = lda; g.transa = ta;
    g.B = B; g.ldb = ldb;
    g.C = C; g.ldc = ldc;
    g.crow = cr; g.crs = crs;
    g.S = S; g.lds = lds;
    g.K = K; g.ntiles = ntiles; g.tile_base = base; g.epi = epi; g.nch = 0;
    return g;
}

extern "C" void kernel_launch(void* const* d_in, const int* in_sizes, int n_in,
                              void* d_out, int out_size) {
    const float* x0  = (const float*)d_in[0];
    const float* x1  = (const float*)d_in[1];
    const float* x2  = (const float*)d_in[2];
    const float* b1  = (const float*)d_in[3];
    const float* b2  = (const float*)d_in[4];
    const float* l0  = (const float*)d_in[5];
    const float* l1l = (const float*)d_in[6];
    const float* l1u = (const float*)d_in[7];
    const float* l2  = (const float*)d_in[8];
    const float* d1  = (const float*)d_in[9];
    const float* d3  = (const float*)d_in[10];
    const float* d5  = (const float*)d_in[11];
    const float* w0  = (const float*)d_in[12];
    const float* w1  = (const float*)d_in[13];
    const float* w2  = (const float*)d_in[14];
    float* out = (float*)d_out;
    (void)in_sizes; (void)n_in; (void)out_size;

    float *X0cat, *T10, *T20, *X1cat, *T1l, *T2l, *T1u, *T2u, *X2cat, *T12, *T22;
    float *W0, *W1, *W2, *x1s, *x2s;
    cudaGetSymbolAddress((void**)&X0cat, g_X0cat);
    cudaGetSymbolAddress((void**)&T10,   g_T10);
    cudaGetSymbolAddress((void**)&T20,   g_T20);
    cudaGetSymbolAddress((void**)&X1cat, g_X1cat);
    cudaGetSymbolAddress((void**)&T1l,   g_T1l);
    cudaGetSymbolAddress((void**)&T2l,   g_T2l);
    cudaGetSymbolAddress((void**)&T1u,   g_T1u);
    cudaGetSymbolAddress((void**)&T2u,   g_T2u);
    cudaGetSymbolAddress((void**)&X2cat, g_X2cat);
    cudaGetSymbolAddress((void**)&T12,   g_T12);
    cudaGetSymbolAddress((void**)&T22,   g_T22);
    cudaGetSymbolAddress((void**)&W0,    g_W0);
    cudaGetSymbolAddress((void**)&W1,    g_W1);
    cudaGetSymbolAddress((void**)&W2,    g_W2);
    cudaGetSymbolAddress((void**)&x1s,   g_x1s);
    cudaGetSymbolAddress((void**)&x2s,   g_x2s);

    cudaFuncSetAttribute(gemm_mma, cudaFuncAttributeMaxDynamicSharedMemorySize, SMEM_BYTES);

    // Prep
    pack_kernel<<<64, 256>>>(W0, w0, 6);
    pack_kernel<<<64, 256>>>(W1, w1, 8);
    pack_kernel<<<64, 256>>>(W2, w2, 6);
    copy_kernel<<<CN0 * 32 / 256, 256>>>(X0cat,       x0, CN0);
    copy_kernel<<<CN1 * 32 / 256, 256>>>(X1cat,       x1, CN1);
    copy_kernel<<<CN2 * 32 / 256, 256>>>(X2cat + 128, x2, CN2);
    scale_copy_kernel<<<CN1 * 32 / 256, 256>>>(x1s, x1, d5, CN1 + 1, CN1);
    scale_copy_kernel<<<CN2 * 32 / 256, 256>>>(x2s, x2, d3, CN2 + 1, CN2);

    // Wave 1: projections — 56 CTAs (256-row tiles)
    BatchArgs ba; ba.nd = 3;
    ba.d[0] = mk(b1, CN1, 0, x1, 128, X0cat + 128, 256,
                 d1, CN0 + 1, nullptr, 0, CN1, 1, 0, 0);
    ba.d[1] = mk(b2, CN2, 0, x2s, 128, X1cat + 128, 256,
                 nullptr, 0, nullptr, 0, CN2, 1, 8, 0);
    ba.d[2] = mk(b2, CN2, 1, x1s, 128, X2cat, 256,
                 nullptr, 0, nullptr, 0, CN1, 1, 40, 0);
    gemm_mma<<<56, 256, SMEM_BYTES>>>(ba);

    // Wave 2: T1 = L @ X — 144 CTAs (~one full chip wave)
    BatchArgs bb; bb.nd = 4;
    bb.d[0] = mk(l0,  CN0, 0, X0cat, 256, T10, 256,
                 nullptr, 0, nullptr, 0, CN0, 2, 0, 0);
    bb.d[1] = mk(l1l, CN1, 0, x1,    128, T1l, 128,
                 nullptr, 0, nullptr, 0, CN1, 1, 16, 0);
    bb.d[2] = mk(l1u, CN1, 0, X1cat, 256, T1u, 256,
                 nullptr, 0, nullptr, 0, CN1, 2, 48, 0);
    bb.d[3] = mk(l2,  CN2, 0, X2cat, 256, T12, 256,
                 nullptr, 0, nullptr, 0, CN2, 2, 112, 0);
    gemm_mma<<<144, 256, SMEM_BYTES>>>(bb);

    // Wave 3: T2 = 2 L T1 - X — 144 CTAs
    BatchArgs bc; bc.nd = 4;
    bc.d[0] = mk(l0,  CN0, 0, T10, 256, T20, 256,
                 nullptr, 0, X0cat, 256, CN0, 2, 0, 1);
    bc.d[1] = mk(l1l, CN1, 0, T1l, 128, T2l, 128,
                 nullptr, 0, x1, 128, CN1, 1, 16, 1);
    bc.d[2] = mk(l1u, CN1, 0, T1u, 256, T2u, 256,
                 nullptr, 0, X1cat, 256, CN1, 2, 48, 1);
    bc.d[3] = mk(l2,  CN2, 0, T12, 256, T22, 256,
                 nullptr, 0, X2cat, 256, CN2, 2, 112, 1);
    gemm_mma<<<144, 256, SMEM_BYTES>>>(bc);

    // Wave 4: combine + relu — 56 CTAs (multi-channel K)
    BatchArgs bd; bd.nd = 3;
    {
        GemmDesc g = mk(nullptr, 0, 0, W0, 128, out, 128,
                        nullptr, 0, nullptr, 0, 6 * 128, 1, 0, 2);
        g.nch = 6;
        const float* ch[6] = {X0cat, T10, T20, X0cat + 128, T10 + 128, T20 + 128};
        for (int c = 0; c < 6; c++) { g.Achan[c] = ch[c]; g.Alda[c] = 256; }
        bd.d[0] = g;
    }
    {
        GemmDesc g = mk(nullptr, 0, 0, W1, 128, out + (size_t)CN0 * 128, 128,
                        nullptr, 0, nullptr, 0, 8 * 128, 1, 8, 2);
        g.nch = 8;
        const float* ch[8] = {X1cat, T1l, T2l, T1u, T2u,
                              X1cat + 128, T1u + 128, T2u + 128};
        int ld[8] = {256, 128, 128, 256, 256, 256, 256, 256};
        for (int c = 0; c < 8; c++) { g.Achan[c] = ch[c]; g.Alda[c] = ld[c]; }
        bd.d[1] = g;
    }
    {
        GemmDesc g = mk(nullptr, 0, 0, W2, 128, out + (size_t)(CN0 + CN1) * 128, 128,
                        nullptr, 0, nullptr, 0, 6 * 128, 1, 40, 2);
        g.nch = 6;
        const float* ch[6] = {X2cat, T12, T22, X2cat + 128, T12 + 128, T22 + 128};
        for (int c = 0; c < 6; c++) { g.Achan[c] = ch[c]; g.Alda[c] = 256; }
        bd.d[2] = g;
    }
    gemm_mma<<<56, 256, SMEM_BYTES>>>(bd);
}

// round 14
// speedup vs baseline: 1.0037x; 1.0037x over previous
#include <cuda_runtime.h>
#include <cuda_bf16.h>
#include <cstdint>

#define CN0 2048
#define CN1 8192
#define CN2 4096

// ---------------------------------------------------------------------------
// Scratch (device globals — no allocation allowed)
// ---------------------------------------------------------------------------
__device__ float g_X0cat[CN0 * 256];   // [x0 | x0p]
__device__ float g_T10[CN0 * 256];
__device__ float g_T20[CN0 * 256];
__device__ float g_X1cat[CN1 * 256];   // [x1 | x1p]
__device__ float g_T1l[CN1 * 128];
__device__ float g_T2l[CN1 * 128];
__device__ float g_T1u[CN1 * 256];
__device__ float g_T2u[CN1 * 256];
__device__ float g_X2cat[CN2 * 256];   // [x2n | x2]
__device__ float g_T12[CN2 * 256];
__device__ float g_T22[CN2 * 256];
__device__ float g_W0[6 * 16384];      // repacked [c][i][o]
__device__ float g_W1[8 * 16384];
__device__ float g_W2[6 * 16384];
__device__ float g_x1s[CN1 * 128];     // d5_pinv * x1 (pre-scaled)
__device__ float g_x2s[CN2 * 128];     // d3 * x2 (pre-scaled)

// ---------------------------------------------------------------------------
// Helpers (sm_80-level features ONLY — harness compiles for plain sm_103)
// ---------------------------------------------------------------------------
__device__ __forceinline__ uint32_t smem_u32(const void* p) {
    uint32_t a;
    asm("{ .reg .u64 t; cvta.to.shared.u64 t, %1; cvt.u32.u64 %0, t; }"
        : "=r"(a) : "l"(p));
    return a;
}
__device__ __forceinline__ uint32_t swz(uint32_t off) {
    return off ^ ((off >> 3) & 0x70u);   // SW128 swizzle for 128B rows
}
__device__ __forceinline__ void ldm4(uint32_t addr, uint32_t r[4]) {
    asm volatile("ldmatrix.sync.aligned.m8n8.x4.shared.b16 {%0,%1,%2,%3}, [%4];"
                 : "=r"(r[0]), "=r"(r[1]), "=r"(r[2]), "=r"(r[3]) : "r"(addr));
}
__device__ __forceinline__ void mma16816(float d[4], const uint32_t a[4],
                                         uint32_t b0, uint32_t b1) {
    asm volatile("mma.sync.aligned.m16n8k16.row.col.f32.bf16.bf16.f32 "
                 "{%0,%1,%2,%3}, {%4,%5,%6,%7}, {%8,%9}, {%0,%1,%2,%3};"
                 : "+f"(d[0]), "+f"(d[1]), "+f"(d[2]), "+f"(d[3])
                 : "r"(a[0]), "r"(a[1]), "r"(a[2]), "r"(a[3]), "r"(b0), "r"(b1));
}

// ---------------------------------------------------------------------------
// bf16 hi/lo split + swizzled STS
// ---------------------------------------------------------------------------
__device__ __forceinline__ void split8(const float4& v0, const float4& v1,
                                       uint4& hi, uint4& lo) {
    float a[8] = {v0.x, v0.y, v0.z, v0.w, v1.x, v1.y, v1.z, v1.w};
    uint32_t h[4], l[4];
#pragma unroll
    for (int p = 0; p < 4; p++) {
        __nv_bfloat162 hb = __floats2bfloat162_rn(a[2 * p], a[2 * p + 1]);
        float hx = __bfloat162float(hb.x), hy = __bfloat162float(hb.y);
        __nv_bfloat162 lb = __floats2bfloat162_rn(a[2 * p] - hx, a[2 * p + 1] - hy);
        h[p] = *(uint32_t*)&hb;
        l[p] = *(uint32_t*)&lb;
    }
    hi = make_uint4(h[0], h[1], h[2], h[3]);
    lo = make_uint4(l[0], l[1], l[2], l[3]);
}
__device__ __forceinline__ void sts128(char* base, uint32_t off, const uint4& v) {
    *(uint4*)(base + swz(off)) = v;
}

// ---------------------------------------------------------------------------
// Quarter-chunk staged loaders. CTA tile: A [256m x 64k], B [128n x 64k].
// Quarter = K=16 slice: A stage 4 float4 (16 regs), B stage 2 float4 (8 regs).
// 256 threads. q = quarter index 0..3.
// ---------------------------------------------------------------------------
__device__ __forceinline__ void ldgA_n_q(float4* st, const float* __restrict__ A,
                                         int lda, int m0, int kb, int t) {
#pragma unroll
    for (int l = 0; l < 2; l++) {
        int idx = t + (l << 8);
        int m = idx >> 1, kg = idx & 1;
        const float* p = A + (size_t)(m0 + m) * lda + kb + 8 * kg;
        st[2 * l]     = *(const float4*)p;
        st[2 * l + 1] = *(const float4*)(p + 4);
    }
}
__device__ __forceinline__ void stsA_n_q(char* hi, char* lo, const float4* st,
                                         int q, int t) {
#pragma unroll
    for (int l = 0; l < 2; l++) {
        int idx = t + (l << 8);
        int m = idx >> 1, kg = idx & 1;
        uint4 h, w;
        split8(st[2 * l], st[2 * l + 1], h, w);
        uint32_t off = (uint32_t)(m * 128 + q * 32 + kg * 16);
        sts128(hi, off, h);
        sts128(lo, off, w);
    }
}
// Transposed A: thread t owns m = t, reads 16 k-strided values
__device__ __forceinline__ void ldgA_t_q(float4* st, const float* __restrict__ A,
                                         int lda, int m0, int kb, int t) {
    const float* p = A + (size_t)kb * lda + m0 + t;
#pragma unroll
    for (int l = 0; l < 4; l++) {
        float4 v;
        v.x = p[0];
        v.y = p[(size_t)lda];
        v.z = p[(size_t)2 * lda];
        v.w = p[(size_t)3 * lda];
        st[l] = v;
        p += (size_t)4 * lda;
    }
}
__device__ __forceinline__ void stsA_t_q(char* hi, char* lo, const float4* st,
                                         int q, int t) {
#pragma unroll
    for (int l = 0; l < 2; l++) {
        uint4 h, w;
        split8(st[2 * l], st[2 * l + 1], h, w);
        uint32_t off = (uint32_t)(t * 128 + q * 32 + l * 16);
        sts128(hi, off, h);
        sts128(lo, off, w);
    }
}
// B: n = t&127, k-half = t>>7 (8 strided k each)
__device__ __forceinline__ void ldgB_q(float4* st, const float* __restrict__ B,
                                       int ldb, int n0, int kb, int t) {
    int n = t & 127, kh = t >> 7;
    const float* p = B + (size_t)(kb + 8 * kh) * ldb + n0 + n;
    float4 v0, v1;
    v0.x = p[0];
    v0.y = p[(size_t)ldb];
    v0.z = p[(size_t)2 * ldb];
    v0.w = p[(size_t)3 * ldb];
    p += (size_t)4 * ldb;
    v1.x = p[0];
    v1.y = p[(size_t)ldb];
    v1.z = p[(size_t)2 * ldb];
    v1.w = p[(size_t)3 * ldb];
    st[0] = v0;
    st[1] = v1;
}
__device__ __forceinline__ void stsB_q(char* hi, char* lo, const float4* st,
                                       int q, int t) {
    int n = t & 127, kh = t >> 7;
    uint4 h, w;
    split8(st[0], st[1], h, w);
    uint32_t off = (uint32_t)(n * 128 + q * 32 + kh * 16);
    sts128(hi, off, h);
    sts128(lo, off, w);
}

// ---------------------------------------------------------------------------
// Batched GEMM descriptors
// ---------------------------------------------------------------------------
struct GemmDesc {
    const float* A;
    const float* B;
    const float* S;
    const float* crow;
    const float* Achan[8];
    float* C;
    int Alda[8];
    int lda, ldb, lds, ldc, crs;
    int K, ntiles, tile_base, transa, epi, nch;  // epi: 0=scale, 1=2AB-S, 2=relu
};
struct BatchArgs { GemmDesc d[4]; int nd; };

__device__ __forceinline__ void ldg_q(float4* stA, float4* stB, const GemmDesc& g,
                                      int m0, int n0, int k0, int q, int t) {
    int kb = k0 + q * 16;
    if (g.nch) {
        int c = k0 >> 7;
        int kin = (k0 & 127) + q * 16;
        ldgA_n_q(stA, g.Achan[c], g.Alda[c], m0, kin, t);
        ldgB_q(stB, g.B + (size_t)c * 16384, 128, 0, kin, t);
    } else if (g.transa) {
        ldgA_t_q(stA, g.A, g.lda, m0, kb, t);
        ldgB_q(stB, g.B, g.ldb, n0, kb, t);
    } else {
        ldgA_n_q(stA, g.A, g.lda, m0, kb, t);
        ldgB_q(stB, g.B, g.ldb, n0, kb, t);
    }
}
// Panel layout within stage: aHi 32KB | aLo 32KB | bHi 16KB | bLo 16KB
#define PAN_ALO 32768
#define PAN_BHI 65536
#define PAN_BLO 81920
#define STAGE_BYTES 98304
#define SMEM_BYTES (2 * STAGE_BYTES + 1024)

__device__ __forceinline__ void sts_q(char* stg, const float4* stA, const float4* stB,
                                      int amode, int q, int t) {
    if (amode) stsA_t_q(stg, stg + PAN_ALO, stA, q, t);
    else       stsA_n_q(stg, stg + PAN_ALO, stA, q, t);
    stsB_q(stg + PAN_BHI, stg + PAN_BLO, stB, q, t);
}

// Compute one K=16 quarter (kk = q): warp tile 64m x 64n, 3-product bf16 comp.
// B fragments loaded once (32 regs); A fragments per-mt (8 regs live).
__device__ __forceinline__ void compute_quarter(uint32_t s, int wm, int wn, int lane,
                                                int kk, float acc[4][8][4]) {
    uint32_t sAh = s, sAl = s + PAN_ALO, sBh = s + PAN_BHI, sBl = s + PAN_BLO;
    uint32_t bh[4][4], bl[4][4];
#pragma unroll
    for (int ng = 0; ng < 4; ng++) {
        int r = lane & 7, part = lane >> 3;
        int n = wn * 64 + ng * 16 + r + ((part >> 1) << 3);
        uint32_t so = swz((uint32_t)(n * 128 + kk * 32 + ((part & 1) << 4)));
        ldm4(sBh + so, bh[ng]);
        ldm4(sBl + so, bl[ng]);
    }
#pragma unroll
    for (int mt = 0; mt < 4; mt++) {
        uint32_t ah[4], al[4];
        uint32_t so = swz((uint32_t)((wm * 64 + mt * 16 + (lane & 15)) * 128
                                     + kk * 32 + ((lane >> 4) << 4)));
        ldm4(sAh + so, ah);
        ldm4(sAl + so, al);
#pragma unroll
        for (int ng = 0; ng < 4; ng++)
#pragma unroll
            for (int hh = 0; hh < 2; hh++) {
                int nt = ng * 2 + hh;
                mma16816(acc[mt][nt], ah, bh[ng][hh * 2], bh[ng][hh * 2 + 1]);
                mma16816(acc[mt][nt], ah, bl[ng][hh * 2], bl[ng][hh * 2 + 1]);
                mma16816(acc[mt][nt], al, bh[ng][hh * 2], bh[ng][hh * 2 + 1]);
            }
    }
}

__global__ __launch_bounds__(256, 1) void gemm_mma(BatchArgs args) {
    extern __shared__ char smem_raw[];
    uint32_t sb = smem_u32(smem_raw);
    uint32_t al1k = (sb + 1023u) & ~1023u;
    char* st0 = smem_raw + (al1k - sb);
    uint32_t sb0 = al1k;

    int t = threadIdx.x;
    int lane = t & 31;
    int warp = t >> 5;
    int wm = warp >> 1, wn = warp & 1;
    int bid = blockIdx.x;

    int di = 0;
#pragma unroll
    for (int i = 1; i < 4; i++)
        if (i < args.nd && bid >= args.d[i].tile_base) di = i;
    const GemmDesc& g = args.d[di];

    int tile = bid - g.tile_base;
    int bm = tile / g.ntiles;
    int bn = tile - bm * g.ntiles;
    int m0 = bm << 8, n0 = bn << 7;                 // 256m x 128n CTA tile
    int amode = (g.nch == 0 && g.transa) ? 1 : 0;

    float acc[4][8][4];
#pragma unroll
    for (int i = 0; i < 4; i++)
#pragma unroll
        for (int j = 0; j < 8; j++)
#pragma unroll
            for (int k = 0; k < 4; k++) acc[i][j][k] = 0.0f;

    int NC = g.K >> 6;

    float4 stA[4], stB[2];
#pragma unroll
    for (int q = 0; q < 4; q++) {
        ldg_q(stA, stB, g, m0, n0, 0, q, t);
        sts_q(st0, stA, stB, amode, q, t);
    }
    __syncthreads();

#pragma unroll 1
    for (int ci = 0; ci < NC; ci++) {
        int more = (ci + 1 < NC);
        char* nbuf = st0 + ((ci + 1) & 1) * STAGE_BYTES;
        uint32_t s = sb0 + (ci & 1) * STAGE_BYTES;
#pragma unroll
        for (int q = 0; q < 4; q++) {
            if (more) ldg_q(stA, stB, g, m0, n0, (ci + 1) << 6, q, t);
            compute_quarter(s, wm, wn, lane, q, acc);
            if (more) sts_q(nbuf, stA, stB, amode, q, t);
        }
        __syncthreads();
    }

    // Epilogue: rows r0 = m0+wm*64+mt*16+(lane>>2), r1 = r0+8;
    //           cols c = n0+wn*64+nt*8+(lane&3)*2
    int ldc = g.ldc;
#pragma unroll
    for (int mt = 0; mt < 4; mt++) {
        int r0 = m0 + wm * 64 + mt * 16 + (lane >> 2);
        int r1 = r0 + 8;
        float s0 = 1.0f, s1 = 1.0f;
        if (g.epi == 0 && g.crow) {
            s0 = g.crow[(size_t)r0 * g.crs];
            s1 = g.crow[(size_t)r1 * g.crs];
        }
        float* C0 = g.C + (size_t)r0 * ldc;
        float* C1 = g.C + (size_t)r1 * ldc;
        const float* S0 = nullptr;
        const float* S1 = nullptr;
        if (g.epi == 1) {
            S0 = g.S + (size_t)r0 * g.lds;
            S1 = g.S + (size_t)r1 * g.lds;
        }
#pragma unroll
        for (int nt = 0; nt < 8; nt++) {
            int c = n0 + wn * 64 + nt * 8 + ((lane & 3) << 1);
            float d0 = acc[mt][nt][0], d1 = acc[mt][nt][1];
            float d2 = acc[mt][nt][2], d3 = acc[mt][nt][3];
            if (g.epi == 0) {
                *(float2*)(C0 + c) = make_float2(d0 * s0, d1 * s0);
                *(float2*)(C1 + c) = make_float2(d2 * s1, d3 * s1);
            } else if (g.epi == 1) {
                float2 sv0 = *(const float2*)(S0 + c);
                float2 sv1 = *(const float2*)(S1 + c);
                *(float2*)(C0 + c) = make_float2(2.f * d0 - sv0.x, 2.f * d1 - sv0.y);
                *(float2*)(C1 + c) = make_float2(2.f * d2 - sv1.x, 2.f * d3 - sv1.y);
            } else {
                *(float2*)(C0 + c) = make_float2(fmaxf(d0, 0.f), fmaxf(d1, 0.f));
                *(float2*)(C1 + c) = make_float2(fmaxf(d2, 0.f), fmaxf(d3, 0.f));
            }
        }
    }
}

// ---------------------------------------------------------------------------
// Prep kernels
// ---------------------------------------------------------------------------
__global__ void pack_kernel(float* __restrict__ dst, const float* __restrict__ w, int nk) {
    int idx = blockIdx.x * 256 + threadIdx.x;
    if (idx < 16384) {
        for (int c = 0; c < nk; c++) dst[c * 16384 + idx] = w[idx * nk + c];
    }
}
__global__ void copy_kernel(float* __restrict__ dst, const float* __restrict__ src, int rows) {
    int idx = blockIdx.x * 256 + threadIdx.x;
    int r = idx >> 5, q = (idx & 31) << 2;
    if (r < rows)
        *(float4*)(dst + (size_t)r * 256 + q) = *(const float4*)(src + (size_t)r * 128 + q);
}
__global__ void scale_copy_kernel(float* __restrict__ dst, const float* __restrict__ src,
                                  const float* __restrict__ diag, int ds, int rows) {
    int idx = blockIdx.x * 256 + threadIdx.x;
    int r = idx >> 5, q = (idx & 31) << 2;
    if (r < rows) {
        float s = diag[(size_t)r * ds];
        float4 v = *(const float4*)(src + (size_t)r * 128 + q);
        v.x *= s; v.y *= s; v.z *= s; v.w *= s;
        *(float4*)(dst + (size_t)r * 128 + q) = v;
    }
}

// ---------------------------------------------------------------------------
// Host launcher
// ---------------------------------------------------------------------------
static GemmDesc mk(const float* A, int lda, int ta,
                   const float* B, int ldb,
                   float* C, int ldc,
                   const float* cr, int crs,
                   const float* S, int lds,
                   int K, int ntiles, int base, int epi) {
    GemmDesc g{};
    g.A = A; g.lda = lda; g.transa = ta;
    g.B = B; g.ldb = ldb;
    g.C = C; g.ldc = ldc;
    g.crow = cr; g.crs = crs;
    g.S = S; g.lds = lds;
    g.K = K; g.ntiles = ntiles; g.tile_base = base; g.epi = epi; g.nch = 0;
    return g;
}

extern "C" void kernel_launch(void* const* d_in, const int* in_sizes, int n_in,
                              void* d_out, int out_size) {
    const float* x0  = (const float*)d_in[0];
    const float* x1  = (const float*)d_in[1];
    const float* x2  = (const float*)d_in[2];
    const float* b1  = (const float*)d_in[3];
    const float* b2  = (const float*)d_in[4];
    const float* l0  = (const float*)d_in[5];
    const float* l1l = (const float*)d_in[6];
    const float* l1u = (const float*)d_in[7];
    const float* l2  = (const float*)d_in[8];
    const float* d1  = (const float*)d_in[9];
    const float* d3  = (const float*)d_in[10];
    const float* d5  = (const float*)d_in[11];
    const float* w0  = (const float*)d_in[12];
    const float* w1  = (const float*)d_in[13];
    const float* w2  = (const float*)d_in[14];
    float* out = (float*)d_out;
    (void)in_sizes; (void)n_in; (void)out_size;

    float *X0cat, *T10, *T20, *X1cat, *T1l, *T2l, *T1u, *T2u, *X2cat, *T12, *T22;
    float *W0, *W1, *W2, *x1s, *x2s;
    cudaGetSymbolAddress((void**)&X0cat, g_X0cat);
    cudaGetSymbolAddress((void**)&T10,   g_T10);
    cudaGetSymbolAddress((void**)&T20,   g_T20);
    cudaGetSymbolAddress((void**)&X1cat, g_X1cat);
    cudaGetSymbolAddress((void**)&T1l,   g_T1l);
    cudaGetSymbolAddress((void**)&T2l,   g_T2l);
    cudaGetSymbolAddress((void**)&T1u,   g_T1u);
    cudaGetSymbolAddress((void**)&T2u,   g_T2u);
    cudaGetSymbolAddress((void**)&X2cat, g_X2cat);
    cudaGetSymbolAddress((void**)&T12,   g_T12);
    cudaGetSymbolAddress((void**)&T22,   g_T22);
    cudaGetSymbolAddress((void**)&W0,    g_W0);
    cudaGetSymbolAddress((void**)&W1,    g_W1);
    cudaGetSymbolAddress((void**)&W2,    g_W2);
    cudaGetSymbolAddress((void**)&x1s,   g_x1s);
    cudaGetSymbolAddress((void**)&x2s,   g_x2s);

    cudaFuncSetAttribute(gemm_mma, cudaFuncAttributeMaxDynamicSharedMemorySize, SMEM_BYTES);

    // Prep
    pack_kernel<<<64, 256>>>(W0, w0, 6);
    pack_kernel<<<64, 256>>>(W1, w1, 8);
    pack_kernel<<<64, 256>>>(W2, w2, 6);
    copy_kernel<<<CN0 * 32 / 256, 256>>>(X0cat,       x0, CN0);
    copy_kernel<<<CN1 * 32 / 256, 256>>>(X1cat,       x1, CN1);
    copy_kernel<<<CN2 * 32 / 256, 256>>>(X2cat + 128, x2, CN2);
    scale_copy_kernel<<<CN1 * 32 / 256, 256>>>(x1s, x1, d5, CN1 + 1, CN1);
    scale_copy_kernel<<<CN2 * 32 / 256, 256>>>(x2s, x2, d3, CN2 + 1, CN2);

    // Wave 1: projections — 56 CTAs (256-row tiles)
    BatchArgs ba; ba.nd = 3;
    ba.d[0] = mk(b1, CN1, 0, x1, 128, X0cat + 128, 256,
                 d1, CN0 + 1, nullptr, 0, CN1, 1, 0, 0);
    ba.d[1] = mk(b2, CN2, 0, x2s, 128, X1cat + 128, 256,
                 nullptr, 0, nullptr, 0, CN2, 1, 8, 0);
    ba.d[2] = mk(b2, CN2, 1, x1s, 128, X2cat, 256,
                 nullptr, 0, nullptr, 0, CN1, 1, 40, 0);
    gemm_mma<<<56, 256, SMEM_BYTES>>>(ba);

    // Wave 2: T1 = L @ X — 144 CTAs (~one full chip wave)
    BatchArgs bb; bb.nd = 4;
    bb.d[0] = mk(l0,  CN0, 0, X0cat, 256, T10, 256,
                 nullptr, 0, nullptr, 0, CN0, 2, 0, 0);
    bb.d[1] = mk(l1l, CN1, 0, x1,    128, T1l, 128,
                 nullptr, 0, nullptr, 0, CN1, 1, 16, 0);
    bb.d[2] = mk(l1u, CN1, 0, X1cat, 256, T1u, 256,
                 nullptr, 0, nullptr, 0, CN1, 2, 48, 0);
    bb.d[3] = mk(l2,  CN2, 0, X2cat, 256, T12, 256,
                 nullptr, 0, nullptr, 0, CN2, 2, 112, 0);
    gemm_mma<<<144, 256, SMEM_BYTES>>>(bb);

    // Wave 3: T2 = 2 L T1 - X — 144 CTAs
    BatchArgs bc; bc.nd = 4;
    bc.d[0] = mk(l0,  CN0, 0, T10, 256, T20, 256,
                 nullptr, 0, X0cat, 256, CN0, 2, 0, 1);
    bc.d[1] = mk(l1l, CN1, 0, T1l, 128, T2l, 128,
                 nullptr, 0, x1, 128, CN1, 1, 16, 1);
    bc.d[2] = mk(l1u, CN1, 0, T1u, 256, T2u, 256,
                 nullptr, 0, X1cat, 256, CN1, 2, 48, 1);
    bc.d[3] = mk(l2,  CN2, 0, T12, 256, T22, 256,
                 nullptr, 0, X2cat, 256, CN2, 2, 112, 1);
    gemm_mma<<<144, 256, SMEM_BYTES>>>(bc);

    // Wave 4: combine + relu — 56 CTAs (multi-channel K)
    BatchArgs bd; bd.nd = 3;
    {
        GemmDesc g = mk(nullptr, 0, 0, W0, 128, out, 128,
                        nullptr, 0, nullptr, 0, 6 * 128, 1, 0, 2);
        g.nch = 6;
        const float* ch[6] = {X0cat, T10, T20, X0cat + 128, T10 + 128, T20 + 128};
        for (int c = 0; c < 6; c++) { g.Achan[c] = ch[c]; g.Alda[c] = 256; }
        bd.d[0] = g;
    }
    {
        GemmDesc g = mk(nullptr, 0, 0, W1, 128, out + (size_t)CN0 * 128, 128,
                        nullptr, 0, nullptr, 0, 8 * 128, 1, 8, 2);
        g.nch = 8;
        const float* ch[8] = {X1cat, T1l, T2l, T1u, T2u,
                              X1cat + 128, T1u + 128, T2u + 128};
        int ld[8] = {256, 128, 128, 256, 256, 256, 256, 256};
        for (int c = 0; c < 8; c++) { g.Achan[c] = ch[c]; g.Alda[c] = ld[c]; }
        bd.d[1] = g;
    }
    {
        GemmDesc g = mk(nullptr, 0, 0, W2, 128, out + (size_t)(CN0 + CN1) * 128, 128,
                        nullptr, 0, nullptr, 0, 6 * 128, 1, 40, 2);
        g.nch = 6;
        const float* ch[6] = {X2cat, T12, T22, X2cat + 128, T12 + 128, T22 + 128};
        for (int c = 0; c < 6; c++) { g.Achan[c] = ch[c]; g.Alda[c] = 256; }
        bd.d[2] = g;
    }
    gemm_mma<<<56, 256, SMEM_BYTES>>>(bd);
}

// round 15
// speedup vs baseline: 1.3590x; 1.3541x over previous
#include <cuda_runtime.h>
#include <cuda_bf16.h>
#include <cstdint>

#define CN0 2048
#define CN1 8192
#define CN2 4096

// ---------------------------------------------------------------------------
// Scratch (device globals — no allocation allowed)
// ---------------------------------------------------------------------------
__device__ float g_X0cat[CN0 * 256];   // [x0 | x0p]
__device__ float g_T10[CN0 * 256];
__device__ float g_T20[CN0 * 256];
__device__ float g_X1cat[CN1 * 256];   // [x1 | x1p]
__device__ float g_T1l[CN1 * 128];
__device__ float g_T2l[CN1 * 128];
__device__ float g_T1u[CN1 * 256];
__device__ float g_T2u[CN1 * 256];
__device__ float g_X2cat[CN2 * 256];   // [x2n | x2]
__device__ float g_T12[CN2 * 256];
__device__ float g_T22[CN2 * 256];
__device__ float g_W0[6 * 16384];      // repacked [c][i][o]
__device__ float g_W1[8 * 16384];
__device__ float g_W2[6 * 16384];
__device__ float g_x1s[CN1 * 128];     // d5_pinv * x1 (pre-scaled)
__device__ float g_x2s[CN2 * 128];     // d3 * x2 (pre-scaled)

// ---------------------------------------------------------------------------
// Helpers (sm_80-level features ONLY — harness compiles for plain sm_103)
// ---------------------------------------------------------------------------
__device__ __forceinline__ uint32_t smem_u32(const void* p) {
    uint32_t a;
    asm("{ .reg .u64 t; cvta.to.shared.u64 t, %1; cvt.u32.u64 %0, t; }"
        : "=r"(a) : "l"(p));
    return a;
}
__device__ __forceinline__ uint32_t swz(uint32_t off) {
    return off ^ ((off >> 3) & 0x70u);   // SW128 swizzle for 128B rows
}
__device__ __forceinline__ void ldm4(uint32_t addr, uint32_t r[4]) {
    asm volatile("ldmatrix.sync.aligned.m8n8.x4.shared.b16 {%0,%1,%2,%3}, [%4];"
                 : "=r"(r[0]), "=r"(r[1]), "=r"(r[2]), "=r"(r[3]) : "r"(addr));
}
__device__ __forceinline__ void mma16816(float d[4], const uint32_t a[4],
                                         uint32_t b0, uint32_t b1) {
    asm volatile("mma.sync.aligned.m16n8k16.row.col.f32.bf16.bf16.f32 "
                 "{%0,%1,%2,%3}, {%4,%5,%6,%7}, {%8,%9}, {%0,%1,%2,%3};"
                 : "+f"(d[0]), "+f"(d[1]), "+f"(d[2]), "+f"(d[3])
                 : "r"(a[0]), "r"(a[1]), "r"(a[2]), "r"(a[3]), "r"(b0), "r"(b1));
}

// ---------------------------------------------------------------------------
// bf16 hi/lo split + swizzled STS
// ---------------------------------------------------------------------------
__device__ __forceinline__ void split8(const float4& v0, const float4& v1,
                                       uint4& hi, uint4& lo) {
    float a[8] = {v0.x, v0.y, v0.z, v0.w, v1.x, v1.y, v1.z, v1.w};
    uint32_t h[4], l[4];
#pragma unroll
    for (int p = 0; p < 4; p++) {
        __nv_bfloat162 hb = __floats2bfloat162_rn(a[2 * p], a[2 * p + 1]);
        float hx = __bfloat162float(hb.x), hy = __bfloat162float(hb.y);
        __nv_bfloat162 lb = __floats2bfloat162_rn(a[2 * p] - hx, a[2 * p + 1] - hy);
        h[p] = *(uint32_t*)&hb;
        l[p] = *(uint32_t*)&lb;
    }
    hi = make_uint4(h[0], h[1], h[2], h[3]);
    lo = make_uint4(l[0], l[1], l[2], l[3]);
}
__device__ __forceinline__ void sts128(char* base, uint32_t off, const uint4& v) {
    *(uint4*)(base + swz(off)) = v;
}

// ---------------------------------------------------------------------------
// Staged chunk loaders: ldg (gmem -> regs) / sts (split -> smem), 256 threads
// A tile [128m x 64k], B tile [128n x 64k], K-major bf16 hi/lo panels.
// ---------------------------------------------------------------------------
__device__ __forceinline__ void ldgA_n(float4* st, const float* __restrict__ A,
                                       int lda, int m0, int k0, int t) {
    const float* Ab = A + (size_t)m0 * lda + k0;
#pragma unroll
    for (int l = 0; l < 4; l++) {
        int idx = t + l * 256;
        int m = idx >> 3, kg = idx & 7;
        const float* p = Ab + (size_t)m * lda + kg * 8;
        st[2 * l]     = *(const float4*)p;
        st[2 * l + 1] = *(const float4*)(p + 4);
    }
}
__device__ __forceinline__ void stsA_n(char* hi, char* lo, const float4* st, int t) {
#pragma unroll
    for (int l = 0; l < 4; l++) {
        int idx = t + l * 256;
        int m = idx >> 3, kg = idx & 7;
        uint4 h, lw;
        split8(st[2 * l], st[2 * l + 1], h, lw);
        uint32_t off = (uint32_t)(m * 128 + kg * 16);
        sts128(hi, off, h);
        sts128(lo, off, lw);
    }
}
// Transposed-A / B gather pattern: fixed m(or n) = t&127, kg = (t>>7)+2l
__device__ __forceinline__ void ldg_kt(float4* st, const float* __restrict__ A,
                                       int lda, int col0, int k0, int t) {
    int m = t & 127;
    const float* Ab = A + (size_t)k0 * lda + col0 + m;
#pragma unroll
    for (int l = 0; l < 4; l++) {
        int kg = (t >> 7) + l * 2;
        const float* p = Ab + (size_t)kg * 8 * lda;
        float4 v0, v1;
        v0.x = p[0];
        v0.y = p[(size_t)lda];
        v0.z = p[(size_t)2 * lda];
        v0.w = p[(size_t)3 * lda];
        v1.x = p[(size_t)4 * lda];
        v1.y = p[(size_t)5 * lda];
        v1.z = p[(size_t)6 * lda];
        v1.w = p[(size_t)7 * lda];
        st[2 * l]     = v0;
        st[2 * l + 1] = v1;
    }
}
__device__ __forceinline__ void sts_kt(char* hi, char* lo, const float4* st, int t) {
    int m = t & 127;
#pragma unroll
    for (int l = 0; l < 4; l++) {
        int kg = (t >> 7) + l * 2;
        uint4 h, lw;
        split8(st[2 * l], st[2 * l + 1], h, lw);
        uint32_t off = (uint32_t)(m * 128 + kg * 16);
        sts128(hi, off, h);
        sts128(lo, off, lw);
    }
}

// ---------------------------------------------------------------------------
// Batched GEMM descriptors
// ---------------------------------------------------------------------------
struct GemmDesc {
    const float* A;
    const float* B;
    const float* S;
    const float* crow;
    const float* Achan[8];
    float* C;
    int Alda[8];
    int lda, ldb, lds, ldc, crs;
    int K, ntiles, tile_base, transa, epi, nch;  // epi: 0=scale, 1=2AB-S, 2=relu
};
struct BatchArgs { GemmDesc d[4]; int nd; };

__device__ __forceinline__ void ldg_chunk(float4* stA, float4* stB, const GemmDesc& g,
                                          int m0, int n0, int k0, int t) {
    if (g.nch) {
        int c = k0 >> 7, kin = k0 & 127;
        ldgA_n(stA, g.Achan[c], g.Alda[c], m0, kin, t);
        ldg_kt(stB, g.B + (size_t)c * 16384, 128, 0, kin, t);
    } else if (g.transa) {
        ldg_kt(stA, g.A, g.lda, m0, k0, t);
        ldg_kt(stB, g.B, g.ldb, n0, k0, t);
    } else {
        ldgA_n(stA, g.A, g.lda, m0, k0, t);
        ldg_kt(stB, g.B, g.ldb, n0, k0, t);
    }
}
__device__ __forceinline__ void sts_chunk(char* stg, const float4* stA, const float4* stB,
                                          int t, int amode) {
    char* aHi = stg;
    char* aLo = stg + 16384;
    char* bHi = stg + 32768;
    char* bLo = stg + 49152;
    if (amode) sts_kt(aHi, aLo, stA, t);
    else       stsA_n(aHi, aLo, stA, t);
    sts_kt(bHi, bLo, stB, t);
}

// Inner compute over one K=64 chunk: warp tile 32m x 64n, 3-product bf16 comp.
// Product-major MMA order: all 16 accumulators touched per pass, so no
// back-to-back RAW chains on any accumulator (was 3 dependent HMMAs).
__device__ __forceinline__ void compute_chunk(uint32_t sAh, uint32_t sAl,
                                              uint32_t sBh, uint32_t sBl,
                                              int wm, int wn, int lane,
                                              float acc[2][8][4]) {
#pragma unroll
    for (int kk = 0; kk < 4; kk++) {
        uint32_t ah[2][4], al[2][4];
#pragma unroll
        for (int mt = 0; mt < 2; mt++) {
            uint32_t off = (uint32_t)((wm * 32 + mt * 16 + (lane & 15)) * 128
                                      + kk * 32 + ((lane >> 4) << 4));
            uint32_t so = swz(off);
            ldm4(sAh + so, ah[mt]);
            ldm4(sAl + so, al[mt]);
        }
        uint32_t bh[4][4], bl[4][4];
#pragma unroll
        for (int ng = 0; ng < 4; ng++) {
            int r = lane & 7, part = lane >> 3;
            int n = wn * 64 + ng * 16 + r + ((part >> 1) << 3);
            uint32_t off = (uint32_t)(n * 128 + kk * 32 + ((part & 1) << 4));
            uint32_t so = swz(off);
            ldm4(sBh + so, bh[ng]);
            ldm4(sBl + so, bl[ng]);
        }
        // pass 1: hiA * hiB — 16 independent MMAs
#pragma unroll
        for (int mt = 0; mt < 2; mt++)
#pragma unroll
            for (int ng = 0; ng < 4; ng++)
#pragma unroll
                for (int h = 0; h < 2; h++)
                    mma16816(acc[mt][ng * 2 + h], ah[mt],
                             bh[ng][h * 2], bh[ng][h * 2 + 1]);
        // pass 2: hiA * loB
#pragma unroll
        for (int mt = 0; mt < 2; mt++)
#pragma unroll
            for (int ng = 0; ng < 4; ng++)
#pragma unroll
                for (int h = 0; h < 2; h++)
                    mma16816(acc[mt][ng * 2 + h], ah[mt],
                             bl[ng][h * 2], bl[ng][h * 2 + 1]);
        // pass 3: loA * hiB
#pragma unroll
        for (int mt = 0; mt < 2; mt++)
#pragma unroll
            for (int ng = 0; ng < 4; ng++)
#pragma unroll
                for (int h = 0; h < 2; h++)
                    mma16816(acc[mt][ng * 2 + h], al[mt],
                             bh[ng][h * 2], bh[ng][h * 2 + 1]);
    }
}

#define STAGE_BYTES 65536
#define SMEM_BYTES (2 * STAGE_BYTES + 1024)

__global__ __launch_bounds__(256, 1) void gemm_mma(BatchArgs args) {
    extern __shared__ char smem_raw[];
    uint32_t sb = smem_u32(smem_raw);
    uint32_t al1k = (sb + 1023u) & ~1023u;
    char* st0 = smem_raw + (al1k - sb);
    uint32_t sb0 = al1k;

    int t = threadIdx.x;
    int lane = t & 31;
    int warp = t >> 5;
    int wm = warp >> 1, wn = warp & 1;
    int bid = blockIdx.x;

    int di = 0;
#pragma unroll
    for (int i = 1; i < 4; i++)
        if (i < args.nd && bid >= args.d[i].tile_base) di = i;
    const GemmDesc& g = args.d[di];

    int tile = bid - g.tile_base;
    int bm = tile / g.ntiles;
    int bn = tile - bm * g.ntiles;
    int m0 = bm << 7, n0 = bn << 7;
    int amode = (g.nch == 0 && g.transa) ? 1 : 0;

    float acc[2][8][4];
#pragma unroll
    for (int i = 0; i < 2; i++)
#pragma unroll
        for (int j = 0; j < 8; j++)
#pragma unroll
            for (int k = 0; k < 4; k++) acc[i][j][k] = 0.0f;

    int NC = g.K >> 6;

    float4 stA[8], stB[8];
    ldg_chunk(stA, stB, g, m0, n0, 0, t);
    sts_chunk(st0, stA, stB, t, amode);
    __syncthreads();

#pragma unroll 1
    for (int ci = 0; ci < NC; ci++) {
        if (ci + 1 < NC)
            ldg_chunk(stA, stB, g, m0, n0, (ci + 1) << 6, t);   // LDG only
        uint32_t s = sb0 + (ci & 1) * STAGE_BYTES;
        compute_chunk(s, s + 16384, s + 32768, s + 49152, wm, wn, lane, acc);
        if (ci + 1 < NC)
            sts_chunk(st0 + ((ci + 1) & 1) * STAGE_BYTES, stA, stB, t, amode);
        __syncthreads();
    }

    // Epilogue: acc[mt][nt] rows r0 = m0+wm*32+mt*16+(lane>>2), r1 = r0+8;
    //           cols c = n0+wn*64+nt*8+(lane&3)*2
    int ldc = g.ldc;
#pragma unroll
    for (int mt = 0; mt < 2; mt++) {
        int r0 = m0 + wm * 32 + mt * 16 + (lane >> 2);
        int r1 = r0 + 8;
        float s0 = 1.0f, s1 = 1.0f;
        if (g.epi == 0 && g.crow) {
            s0 = g.crow[(size_t)r0 * g.crs];
            s1 = g.crow[(size_t)r1 * g.crs];
        }
        float* C0 = g.C + (size_t)r0 * ldc;
        float* C1 = g.C + (size_t)r1 * ldc;
        const float* S0 = nullptr;
        const float* S1 = nullptr;
        if (g.epi == 1) {
            S0 = g.S + (size_t)r0 * g.lds;
            S1 = g.S + (size_t)r1 * g.lds;
        }
#pragma unroll
        for (int nt = 0; nt < 8; nt++) {
            int c = n0 + wn * 64 + nt * 8 + ((lane & 3) << 1);
            float d0 = acc[mt][nt][0], d1 = acc[mt][nt][1];
            float d2 = acc[mt][nt][2], d3 = acc[mt][nt][3];
            if (g.epi == 0) {
                *(float2*)(C0 + c) = make_float2(d0 * s0, d1 * s0);
                *(float2*)(C1 + c) = make_float2(d2 * s1, d3 * s1);
            } else if (g.epi == 1) {
                float2 sv0 = *(const float2*)(S0 + c);
                float2 sv1 = *(const float2*)(S1 + c);
                *(float2*)(C0 + c) = make_float2(2.f * d0 - sv0.x, 2.f * d1 - sv0.y);
                *(float2*)(C1 + c) = make_float2(2.f * d2 - sv1.x, 2.f * d3 - sv1.y);
            } else {
                *(float2*)(C0 + c) = make_float2(fmaxf(d0, 0.f), fmaxf(d1, 0.f));
                *(float2*)(C1 + c) = make_float2(fmaxf(d2, 0.f), fmaxf(d3, 0.f));
            }
        }
    }
}

// ---------------------------------------------------------------------------
// Prep kernels
// ---------------------------------------------------------------------------
__global__ void pack_kernel(float* __restrict__ dst, const float* __restrict__ w, int nk) {
    int idx = blockIdx.x * 256 + threadIdx.x;
    if (idx < 16384) {
        for (int c = 0; c < nk; c++) dst[c * 16384 + idx] = w[idx * nk + c];
    }
}
__global__ void copy_kernel(float* __restrict__ dst, const float* __restrict__ src, int rows) {
    int idx = blockIdx.x * 256 + threadIdx.x;
    int r = idx >> 5, q = (idx & 31) << 2;
    if (r < rows)
        *(float4*)(dst + (size_t)r * 256 + q) = *(const float4*)(src + (size_t)r * 128 + q);
}
__global__ void scale_copy_kernel(float* __restrict__ dst, const float* __restrict__ src,
                                  const float* __restrict__ diag, int ds, int rows) {
    int idx = blockIdx.x * 256 + threadIdx.x;
    int r = idx >> 5, q = (idx & 31) << 2;
    if (r < rows) {
        float s = diag[(size_t)r * ds];
        float4 v = *(const float4*)(src + (size_t)r * 128 + q);
        v.x *= s; v.y *= s; v.z *= s; v.w *= s;
        *(float4*)(dst + (size_t)r * 128 + q) = v;
    }
}

// ---------------------------------------------------------------------------
// Host launcher
// ---------------------------------------------------------------------------
static GemmDesc mk(const float* A, int lda, int ta,
                   const float* B, int ldb,
                   float* C, int ldc,
                   const float* cr, int crs,
                   const float* S, int lds,
                   int K, int ntiles, int base, int epi) {
    GemmDesc g{};
    g.A = A; g.lda = lda; g.transa = ta;
    g.B = B; g.ldb = ldb;
    g.C = C; g.ldc = ldc;
    g.crow = cr; g.crs = crs;
    g.S = S; g.lds = lds;
    g.K = K; g.ntiles = ntiles; g.tile_base = base; g.epi = epi; g.nch = 0;
    return g;
}

extern "C" void kernel_launch(void* const* d_in, const int* in_sizes, int n_in,
                              void* d_out, int out_size) {
    const float* x0  = (const float*)d_in[0];
    const float* x1  = (const float*)d_in[1];
    const float* x2  = (const float*)d_in[2];
    const float* b1  = (const float*)d_in[3];
    const float* b2  = (const float*)d_in[4];
    const float* l0  = (const float*)d_in[5];
    const float* l1l = (const float*)d_in[6];
    const float* l1u = (const float*)d_in[7];
    const float* l2  = (const float*)d_in[8];
    const float* d1  = (const float*)d_in[9];
    const float* d3  = (const float*)d_in[10];
    const float* d5  = (const float*)d_in[11];
    const float* w0  = (const float*)d_in[12];
    const float* w1  = (const float*)d_in[13];
    const float* w2  = (const float*)d_in[14];
    float* out = (float*)d_out;
    (void)in_sizes; (void)n_in; (void)out_size;

    float *X0cat, *T10, *T20, *X1cat, *T1l, *T2l, *T1u, *T2u, *X2cat, *T12, *T22;
    float *W0, *W1, *W2, *x1s, *x2s;
    cudaGetSymbolAddress((void**)&X0cat, g_X0cat);
    cudaGetSymbolAddress((void**)&T10,   g_T10);
    cudaGetSymbolAddress((void**)&T20,   g_T20);
    cudaGetSymbolAddress((void**)&X1cat, g_X1cat);
    cudaGetSymbolAddress((void**)&T1l,   g_T1l);
    cudaGetSymbolAddress((void**)&T2l,   g_T2l);
    cudaGetSymbolAddress((void**)&T1u,   g_T1u);
    cudaGetSymbolAddress((void**)&T2u,   g_T2u);
    cudaGetSymbolAddress((void**)&X2cat, g_X2cat);
    cudaGetSymbolAddress((void**)&T12,   g_T12);
    cudaGetSymbolAddress((void**)&T22,   g_T22);
    cudaGetSymbolAddress((void**)&W0,    g_W0);
    cudaGetSymbolAddress((void**)&W1,    g_W1);
    cudaGetSymbolAddress((void**)&W2,    g_W2);
    cudaGetSymbolAddress((void**)&x1s,   g_x1s);
    cudaGetSymbolAddress((void**)&x2s,   g_x2s);

    cudaFuncSetAttribute(gemm_mma, cudaFuncAttributeMaxDynamicSharedMemorySize, SMEM_BYTES);

    // Prep
    pack_kernel<<<64, 256>>>(W0, w0, 6);
    pack_kernel<<<64, 256>>>(W1, w1, 8);
    pack_kernel<<<64, 256>>>(W2, w2, 6);
    copy_kernel<<<CN0 * 32 / 256, 256>>>(X0cat,       x0, CN0);
    copy_kernel<<<CN1 * 32 / 256, 256>>>(X1cat,       x1, CN1);
    copy_kernel<<<CN2 * 32 / 256, 256>>>(X2cat + 128, x2, CN2);
    scale_copy_kernel<<<CN1 * 32 / 256, 256>>>(x1s, x1, d5, CN1 + 1, CN1);
    scale_copy_kernel<<<CN2 * 32 / 256, 256>>>(x2s, x2, d3, CN2 + 1, CN2);

    // Wave 1: projections — 112 CTAs
    BatchArgs ba; ba.nd = 3;
    ba.d[0] = mk(b1, CN1, 0, x1, 128, X0cat + 128, 256,
                 d1, CN0 + 1, nullptr, 0, CN1, 1, 0, 0);
    ba.d[1] = mk(b2, CN2, 0, x2s, 128, X1cat + 128, 256,
                 nullptr, 0, nullptr, 0, CN2, 1, 16, 0);
    ba.d[2] = mk(b2, CN2, 1, x1s, 128, X2cat, 256,
                 nullptr, 0, nullptr, 0, CN1, 1, 80, 0);
    gemm_mma<<<112, 256, SMEM_BYTES>>>(ba);

    // Wave 2: T1 = L @ X — 288 CTAs
    BatchArgs bb; bb.nd = 4;
    bb.d[0] = mk(l0,  CN0, 0, X0cat, 256, T10, 256,
                 nullptr, 0, nullptr, 0, CN0, 2, 0, 0);
    bb.d[1] = mk(l1l, CN1, 0, x1,    128, T1l, 128,
                 nullptr, 0, nullptr, 0, CN1, 1, 32, 0);
    bb.d[2] = mk(l1u, CN1, 0, X1cat, 256, T1u, 256,
                 nullptr, 0, nullptr, 0, CN1, 2, 96, 0);
    bb.d[3] = mk(l2,  CN2, 0, X2cat, 256, T12, 256,
                 nullptr, 0, nullptr, 0, CN2, 2, 224, 0);
    gemm_mma<<<288, 256, SMEM_BYTES>>>(bb);

    // Wave 3: T2 = 2 L T1 - X — 288 CTAs
    BatchArgs bc; bc.nd = 4;
    bc.d[0] = mk(l0,  CN0, 0, T10, 256, T20, 256,
                 nullptr, 0, X0cat, 256, CN0, 2, 0, 1);
    bc.d[1] = mk(l1l, CN1, 0, T1l, 128, T2l, 128,
                 nullptr, 0, x1, 128, CN1, 1, 32, 1);
    bc.d[2] = mk(l1u, CN1, 0, T1u, 256, T2u, 256,
                 nullptr, 0, X1cat, 256, CN1, 2, 96, 1);
    bc.d[3] = mk(l2,  CN2, 0, T12, 256, T22, 256,
                 nullptr, 0, X2cat, 256, CN2, 2, 224, 1);
    gemm_mma<<<288, 256, SMEM_BYTES>>>(bc);

    // Wave 4: combine + relu — 112 CTAs (multi-channel K)
    BatchArgs bd; bd.nd = 3;
    {
        GemmDesc g = mk(nullptr, 0, 0, W0, 128, out, 128,
                        nullptr, 0, nullptr, 0, 6 * 128, 1, 0, 2);
        g.nch = 6;
        const float* ch[6] = {X0cat, T10, T20, X0cat + 128, T10 + 128, T20 + 128};
        for (int c = 0; c < 6; c++) { g.Achan[c] = ch[c]; g.Alda[c] = 256; }
        bd.d[0] = g;
    }
    {
        GemmDesc g = mk(nullptr, 0, 0, W1, 128, out + (size_t)CN0 * 128, 128,
                        nullptr, 0, nullptr, 0, 8 * 128, 1, 16, 2);
        g.nch = 8;
        const float* ch[8] = {X1cat, T1l, T2l, T1u, T2u,
                              X1cat + 128, T1u + 128, T2u + 128};
        int ld[8] = {256, 128, 128, 256, 256, 256, 256, 256};
        for (int c = 0; c < 8; c++) { g.Achan[c] = ch[c]; g.Alda[c] = ld[c]; }
        bd.d[1] = g;
    }
    {
        GemmDesc g = mk(nullptr, 0, 0, W2, 128, out + (size_t)(CN0 + CN1) * 128, 128,
                        nullptr, 0, nullptr, 0, 6 * 128, 1, 80, 2);
        g.nch = 6;
        const float* ch[6] = {X2cat, T12, T22, X2cat + 128, T12 + 128, T22 + 128};
        for (int c = 0; c < 6; c++) { g.Achan[c] = ch[c]; g.Alda[c] = 256; }
        bd.d[2] = g;
    }
    gemm_mma<<<112, 256, SMEM_BYTES>>>(bd);
}